// round 12
// baseline (speedup 1.0000x reference)
#include <cuda_runtime.h>
#include <cuda_bf16.h>

#define TPB 256
#define N_MAX 100000

// Packed per-node data: pos.xyz + atom_type (bitcast int in .w).
// 16B aligned -> each random gather is exactly one LDG.128 / one line.
__device__ float4 g_node[N_MAX];

__global__ void prep_kernel(const float* __restrict__ pos,
                            const int* __restrict__ types,
                            int N, float* __restrict__ out, int G) {
    int i = blockIdx.x * blockDim.x + threadIdx.x;
    if (i < G) out[i] = 0.0f;           // d_out is poisoned -> zero it
    if (i < N) {
        float4 v;
        v.x = pos[3 * i + 0];
        v.y = pos[3 * i + 1];
        v.z = pos[3 * i + 2];
        v.w = __int_as_float(types[i]);
        g_node[i] = v;
    }
}

__device__ __forceinline__ float poly(const float4& n0, const float4& n1,
                                      const float4* __restrict__ s_k,
                                      const float* __restrict__ s_v) {
    float dx = n0.x - n1.x, dy = n0.y - n1.y, dz = n0.z - n1.z;
    float x  = sqrtf(dx * dx + dy * dy + dz * dz);
    int idx  = __float_as_int(n0.w) * 25 + __float_as_int(n1.w);
    float4 k = s_k[idx];
    return s_v[idx] + x * (k.x + x * (k.y + x * (k.z + x * k.w)));
}

__global__ void __launch_bounds__(TPB, 6)
edge_kernel(const int4* __restrict__ map0,   // mapping row 0, 4 edges per int4
            const int4* __restrict__ map1,   // mapping row 1
            const int4* __restrict__ batch,  // mapping_batch
            const float* __restrict__ ks,    // (4,25,25)
            const float* __restrict__ v0,    // (25,25)
            float* __restrict__ out,
            int nQuads, int quadsPerBlock) {
    __shared__ float4 s_k[625];  // k0..k3 per (t0,t1)
    __shared__ float  s_v[625];  // v0 per (t0,t1)
    for (int i = threadIdx.x; i < 625; i += TPB) {
        s_k[i] = make_float4(ks[i], ks[625 + i], ks[1250 + i], ks[1875 + i]);
        s_v[i] = v0[i];
    }
    __syncthreads();

    int pStart = blockIdx.x * quadsPerBlock + threadIdx.x;
    int pEnd   = min((blockIdx.x + 1) * quadsPerBlock, nQuads);

    // Register accumulator; mapping_batch is sorted so segment changes are
    // rare along a thread's walk -> few atomics.
    float acc = 0.0f;
    int   cur = -1;

    for (int p = pStart; p < pEnd; p += TPB) {
        // Streamed index loads: evict-first, read once.
        int4 a = __ldcs(&map0[p]);
        int4 b = __ldcs(&map1[p]);
        int4 s = __ldcs(&batch[p]);

        // ---- all 8 gathers issued back-to-back: MLP = 8 ----
        float4 na0 = g_node[a.x];
        float4 na1 = g_node[a.y];
        float4 na2 = g_node[a.z];
        float4 na3 = g_node[a.w];
        float4 nb0 = g_node[b.x];
        float4 nb1 = g_node[b.y];
        float4 nb2 = g_node[b.z];
        float4 nb3 = g_node[b.w];

        // ---- branch-free compute of the 4 edge energies ----
        float V0 = poly(na0, nb0, s_k, s_v);
        float V1 = poly(na1, nb1, s_k, s_v);
        float V2 = poly(na2, nb2, s_k, s_v);
        float V3 = poly(na3, nb3, s_k, s_v);

        // ---- segment accumulation (rarely-taken branches) ----
        if (s.x != cur) {
            if (cur >= 0) atomicAdd(&out[cur], acc);
            acc = 0.0f; cur = s.x;
        }
        acc += V0;
        if (s.y != cur) { atomicAdd(&out[cur], acc); acc = 0.0f; cur = s.y; }
        acc += V1;
        if (s.z != cur) { atomicAdd(&out[cur], acc); acc = 0.0f; cur = s.z; }
        acc += V2;
        if (s.w != cur) { atomicAdd(&out[cur], acc); acc = 0.0f; cur = s.w; }
        acc += V3;
    }
    if (cur >= 0) atomicAdd(&out[cur], acc);
}

extern "C" void kernel_launch(void* const* d_in, const int* in_sizes, int n_in,
                              void* d_out, int out_size) {
    const float* pos     = (const float*)d_in[0];
    const float* ks      = (const float*)d_in[1];
    const float* v0      = (const float*)d_in[2];
    const int*   mapping = (const int*)d_in[3];   // JAX downcasts int64 -> int32
    const int*   types   = (const int*)d_in[4];
    const int*   batch   = (const int*)d_in[5];

    int N = in_sizes[0] / 3;          // 100000
    int E = in_sizes[3] / 2;          // 8,000,000
    int G = out_size;                 // 512
    float* out = (float*)d_out;

    if (N > N_MAX) N = N_MAX;  // defensive; problem shape is fixed

    int nQuads = E / 4;        // 2M

    int prepThreads = (N > G) ? N : G;
    prep_kernel<<<(prepThreads + TPB - 1) / TPB, TPB>>>(pos, types, N, out, G);

    // 6 resident 256-thread blocks per SM -> one full wave of 888 blocks.
    int grid = 888;  // 6 * 148
    int qpb  = (nQuads + grid - 1) / grid;
    qpb      = ((qpb + TPB - 1) / TPB) * TPB;  // multiple of block width
    grid     = (nQuads + qpb - 1) / qpb;

    edge_kernel<<<grid, TPB>>>((const int4*)mapping,
                               (const int4*)(mapping + E),
                               (const int4*)batch,
                               ks, v0, out, nQuads, qpb);
}

// round 13
// speedup vs baseline: 1.1751x; 1.1751x over previous
#include <cuda_runtime.h>
#include <cuda_bf16.h>

#define TPB 256
#define N_MAX 100000

// Packed per-node data: pos.xyz + atom_type (bitcast int in .w).
// 16B aligned -> each random gather is exactly one LDG.128 / one line.
__device__ float4 g_node[N_MAX];

__global__ void prep_kernel(const float* __restrict__ pos,
                            const int* __restrict__ types,
                            int N, float* __restrict__ out, int G) {
    int i = blockIdx.x * blockDim.x + threadIdx.x;
    if (i < G) out[i] = 0.0f;           // d_out is poisoned -> zero it
    if (i < N) {
        float4 v;
        v.x = pos[3 * i + 0];
        v.y = pos[3 * i + 1];
        v.z = pos[3 * i + 2];
        v.w = __int_as_float(types[i]);
        g_node[i] = v;
    }
}

__device__ __forceinline__ float poly(const float4& n0, const float4& n1,
                                      const float4* __restrict__ s_k,
                                      const float* __restrict__ s_v) {
    float dx = n0.x - n1.x, dy = n0.y - n1.y, dz = n0.z - n1.z;
    float x  = sqrtf(dx * dx + dy * dy + dz * dz);
    int idx  = __float_as_int(n0.w) * 25 + __float_as_int(n1.w);
    float4 k = s_k[idx];
    return s_v[idx] + x * (k.x + x * (k.y + x * (k.z + x * k.w)));
}

// NOTE: no minBlocksPerMultiprocessor clause — R12 showed that squeezing regs
// below 48 destroys the 8-wide gather MLP (regs buy outstanding loads here).
__global__ void __launch_bounds__(TPB)
edge_kernel(const int4* __restrict__ map0,   // mapping row 0, 4 edges per int4
            const int4* __restrict__ map1,   // mapping row 1
            const int4* __restrict__ batch,  // mapping_batch
            const float* __restrict__ ks,    // (4,25,25)
            const float* __restrict__ v0,    // (25,25)
            float* __restrict__ out,
            int nQuads, int quadsPerBlock) {
    __shared__ float4 s_k[625];  // k0..k3 per (t0,t1)
    __shared__ float  s_v[625];  // v0 per (t0,t1)
    for (int i = threadIdx.x; i < 625; i += TPB) {
        s_k[i] = make_float4(ks[i], ks[625 + i], ks[1250 + i], ks[1875 + i]);
        s_v[i] = v0[i];
    }
    __syncthreads();

    int pStart = blockIdx.x * quadsPerBlock + threadIdx.x;
    int pEnd   = min((blockIdx.x + 1) * quadsPerBlock, nQuads);

    // Register accumulator; mapping_batch is sorted so segment changes are
    // rare along a thread's walk -> few atomics.
    float acc = 0.0f;
    int   cur = -1;

    for (int p = pStart; p < pEnd; p += TPB) {
        // Streamed index loads: evict-first, read once.
        int4 a = __ldcs(&map0[p]);
        int4 b = __ldcs(&map1[p]);
        int4 s = __ldcs(&batch[p]);

        // ---- all 8 gathers issued back-to-back: MLP = 8 ----
        float4 na0 = g_node[a.x];
        float4 na1 = g_node[a.y];
        float4 na2 = g_node[a.z];
        float4 na3 = g_node[a.w];
        float4 nb0 = g_node[b.x];
        float4 nb1 = g_node[b.y];
        float4 nb2 = g_node[b.z];
        float4 nb3 = g_node[b.w];

        // ---- branch-free compute of the 4 edge energies ----
        float V0 = poly(na0, nb0, s_k, s_v);
        float V1 = poly(na1, nb1, s_k, s_v);
        float V2 = poly(na2, nb2, s_k, s_v);
        float V3 = poly(na3, nb3, s_k, s_v);

        // ---- segment accumulation (rarely-taken branches) ----
        if (s.x != cur) {
            if (cur >= 0) atomicAdd(&out[cur], acc);
            acc = 0.0f; cur = s.x;
        }
        acc += V0;
        if (s.y != cur) { atomicAdd(&out[cur], acc); acc = 0.0f; cur = s.y; }
        acc += V1;
        if (s.z != cur) { atomicAdd(&out[cur], acc); acc = 0.0f; cur = s.z; }
        acc += V2;
        if (s.w != cur) { atomicAdd(&out[cur], acc); acc = 0.0f; cur = s.w; }
        acc += V3;
    }
    if (cur >= 0) atomicAdd(&out[cur], acc);
}

extern "C" void kernel_launch(void* const* d_in, const int* in_sizes, int n_in,
                              void* d_out, int out_size) {
    const float* pos     = (const float*)d_in[0];
    const float* ks      = (const float*)d_in[1];
    const float* v0      = (const float*)d_in[2];
    const int*   mapping = (const int*)d_in[3];   // JAX downcasts int64 -> int32
    const int*   types   = (const int*)d_in[4];
    const int*   batch   = (const int*)d_in[5];

    int N = in_sizes[0] / 3;          // 100000
    int E = in_sizes[3] / 2;          // 8,000,000
    int G = out_size;                 // 512
    float* out = (float*)d_out;

    if (N > N_MAX) N = N_MAX;  // defensive; problem shape is fixed

    int nQuads = E / 4;        // 2M

    int prepThreads = (N > G) ? N : G;
    prep_kernel<<<(prepThreads + TPB - 1) / TPB, TPB>>>(pos, types, N, out, G);

    // Full single wave at 5 resident blocks/SM (48 regs -> 5 blocks max).
    // Unpadded chunks keep the wave balanced (no ragged 4-vs-3 split).
    int grid = 740;  // 5 * 148
    int qpb  = (nQuads + grid - 1) / grid;
    grid     = (nQuads + qpb - 1) / qpb;

    edge_kernel<<<grid, TPB>>>((const int4*)mapping,
                               (const int4*)(mapping + E),
                               (const int4*)batch,
                               ks, v0, out, nQuads, qpb);
}

// round 15
// speedup vs baseline: 1.4217x; 1.2098x over previous
#include <cuda_runtime.h>
#include <cuda_bf16.h>

#define TPB 256
#define N_MAX 100000

// Packed per-node data: pos.xyz + atom_type (bitcast int in .w).
// 16B aligned -> each random gather is exactly one LDG.128 / one line.
__device__ float4 g_node[N_MAX];

__global__ void prep_kernel(const float* __restrict__ pos,
                            const int* __restrict__ types,
                            int N, float* __restrict__ out, int G) {
    int i = blockIdx.x * blockDim.x + threadIdx.x;
    if (i < G) out[i] = 0.0f;           // d_out is poisoned -> zero it
    if (i < N) {
        float4 v;
        v.x = pos[3 * i + 0];
        v.y = pos[3 * i + 1];
        v.z = pos[3 * i + 2];
        v.w = __int_as_float(types[i]);
        g_node[i] = v;
    }
}

__device__ __forceinline__ float poly(const float4& n0, const float4& n1,
                                      const float4* __restrict__ s_k,
                                      const float* __restrict__ s_v) {
    float dx = n0.x - n1.x, dy = n0.y - n1.y, dz = n0.z - n1.z;
    float x  = sqrtf(dx * dx + dy * dy + dz * dz);
    int idx  = __float_as_int(n0.w) * 25 + __float_as_int(n1.w);
    float4 k = s_k[idx];
    return s_v[idx] + x * (k.x + x * (k.y + x * (k.z + x * k.w)));
}

// NOTE: no minBlocksPerMultiprocessor clause — R12/R13 showed regs buy MLP
// here, and >4 CTAs/SM only deepens the L1tex queue (monotone regression).
__global__ void __launch_bounds__(TPB)
edge_kernel(const int4* __restrict__ map0,   // mapping row 0, 4 edges per int4
            const int4* __restrict__ map1,   // mapping row 1
            const int4* __restrict__ batch,  // mapping_batch
            const float* __restrict__ ks,    // (4,25,25)
            const float* __restrict__ v0,    // (25,25)
            float* __restrict__ out,
            int nQuads, int quadsPerBlock) {
    __shared__ float4 s_k[625];  // k0..k3 per (t0,t1)
    __shared__ float  s_v[625];  // v0 per (t0,t1)
    for (int i = threadIdx.x; i < 625; i += TPB) {
        s_k[i] = make_float4(ks[i], ks[625 + i], ks[1250 + i], ks[1875 + i]);
        s_v[i] = v0[i];
    }
    __syncthreads();

    int pStart = blockIdx.x * quadsPerBlock + threadIdx.x;
    int pEnd   = min((blockIdx.x + 1) * quadsPerBlock, nQuads);

    float acc = 0.0f;
    int   cur = -1;

    if (pStart < pEnd) {
        // ---- software pipeline: indices for iteration i are loaded during
        // iteration i-1, hiding the ~577cy DRAM stream latency behind the
        // ~240cy L2 gather latency + compute of the previous iteration. ----
        int4 a = __ldcs(&map0[pStart]);
        int4 b = __ldcs(&map1[pStart]);
        int4 s = __ldcs(&batch[pStart]);

        for (int p = pStart; p < pEnd; p += TPB) {
            // ---- all 8 gathers issued back-to-back: MLP = 8 ----
            float4 na0 = g_node[a.x];
            float4 na1 = g_node[a.y];
            float4 na2 = g_node[a.z];
            float4 na3 = g_node[a.w];
            float4 nb0 = g_node[b.x];
            float4 nb1 = g_node[b.y];
            float4 nb2 = g_node[b.z];
            float4 nb3 = g_node[b.w];

            // ---- prefetch next iteration's indices (branchless clamp) ----
            int pn = (p + TPB < pEnd) ? (p + TPB) : p;
            int4 an = __ldcs(&map0[pn]);
            int4 bn = __ldcs(&map1[pn]);
            int4 sn = __ldcs(&batch[pn]);

            // ---- branch-free compute of the 4 edge energies ----
            float V0 = poly(na0, nb0, s_k, s_v);
            float V1 = poly(na1, nb1, s_k, s_v);
            float V2 = poly(na2, nb2, s_k, s_v);
            float V3 = poly(na3, nb3, s_k, s_v);

            // ---- segment accumulation (rarely-taken branches);
            //      mapping_batch sorted -> few atomics ----
            if (s.x != cur) {
                if (cur >= 0) atomicAdd(&out[cur], acc);
                acc = 0.0f; cur = s.x;
            }
            acc += V0;
            if (s.y != cur) { atomicAdd(&out[cur], acc); acc = 0.0f; cur = s.y; }
            acc += V1;
            if (s.z != cur) { atomicAdd(&out[cur], acc); acc = 0.0f; cur = s.z; }
            acc += V2;
            if (s.w != cur) { atomicAdd(&out[cur], acc); acc = 0.0f; cur = s.w; }
            acc += V3;

            a = an; b = bn; s = sn;
        }
    }
    if (cur >= 0) atomicAdd(&out[cur], acc);
}

extern "C" void kernel_launch(void* const* d_in, const int* in_sizes, int n_in,
                              void* d_out, int out_size) {
    const float* pos     = (const float*)d_in[0];
    const float* ks      = (const float*)d_in[1];
    const float* v0      = (const float*)d_in[2];
    const int*   mapping = (const int*)d_in[3];   // JAX downcasts int64 -> int32
    const int*   types   = (const int*)d_in[4];
    const int*   batch   = (const int*)d_in[5];

    int N = in_sizes[0] / 3;          // 100000
    int E = in_sizes[3] / 2;          // 8,000,000
    int G = out_size;                 // 512
    float* out = (float*)d_out;

    if (N > N_MAX) N = N_MAX;  // defensive; problem shape is fixed

    int nQuads = E / 4;        // 2M

    int prepThreads = (N > G) ? N : G;
    prep_kernel<<<(prepThreads + TPB - 1) / TPB, TPB>>>(pos, types, N, out, G);

    // R8's proven config: ~4 blocks/SM target, qpb a multiple of block width.
    int grid = 592;  // 4 * 148
    int qpb  = (nQuads + grid - 1) / grid;
    qpb      = ((qpb + TPB - 1) / TPB) * TPB;
    grid     = (nQuads + qpb - 1) / qpb;

    edge_kernel<<<grid, TPB>>>((const int4*)mapping,
                               (const int4*)(mapping + E),
                               (const int4*)batch,
                               ks, v0, out, nQuads, qpb);
}